// round 3
// baseline (speedup 1.0000x reference)
#include <cuda_runtime.h>

#define GRID  2048
#define TPB   256

// Per-block partials: fully overwritten each launch (graph-deterministic).
__device__ float g_part[GRID];
// Completion counter: atomicInc with wrap GRID-1 returns it to 0 after every
// complete launch, so graph replays see identical state. Zero-init at load.
__device__ unsigned int g_count;

__device__ __forceinline__ float group_loss(float4 p, float4 q, float4 r) {
    float ax = p.y, ay = p.z, az = p.w;
    float bx = q.y, by = q.z, bz = q.w;
    float cx = r.y, cy = r.z, cz = r.w;

    float ia = rsqrtf(ax * ax + ay * ay + az * az);
    float ib = rsqrtf(bx * bx + by * by + bz * bz);
    float ic = rsqrtf(cx * cx + cy * cy + cz * cz);
    ax *= ia; ay *= ia; az *= ia;
    bx *= ib; by *= ib; bz *= ib;
    cx *= ic; cy *= ic; cz *= ic;

    float daa = ax * ax + ay * ay + az * az - 1.0f;
    float dbb = bx * bx + by * by + bz * bz - 1.0f;
    float dcc = cx * cx + cy * cy + cz * cz - 1.0f;
    float dab = ax * bx + ay * by + az * bz;
    float dac = ax * cx + ay * cy + az * cz;
    float dbc = bx * cx + by * cy + bz * cz;

    return daa * daa + dbb * dbb + dcc * dcc
         + 2.0f * (dab * dab + dac * dac + dbc * dbc);
}

__global__ void __launch_bounds__(TPB) loss_kernel(const float4* __restrict__ in,
                                                   int nrows, float* __restrict__ out) {
    const int tid = threadIdx.x;
    float acc = 0.0f;

    // Grid-stride over 256-row tiles; one row per thread, 6 coalesced LDG.128.
    for (int row = blockIdx.x * TPB + tid; row < nrows; row += GRID * TPB) {
        const float4* __restrict__ r = in + (size_t)row * 6;
        float4 r0 = r[0];
        float4 r1 = r[1];
        float4 r2 = r[2];
        float4 r3 = r[3];
        float4 r4 = r[4];
        float4 r5 = r[5];
        acc += group_loss(r0, r1, r2);
        acc += group_loss(r3, r4, r5);
    }

    // Block reduction.
    #pragma unroll
    for (int off = 16; off > 0; off >>= 1)
        acc += __shfl_xor_sync(0xFFFFFFFFu, acc, off);

    __shared__ float ws[TPB / 32];
    __shared__ unsigned int s_ticket;
    const int lane = tid & 31;
    const int warp = tid >> 5;
    if (lane == 0) ws[warp] = acc;
    __syncthreads();

    if (warp == 0) {
        acc = (lane < TPB / 32) ? ws[lane] : 0.0f;
        #pragma unroll
        for (int off = 4; off > 0; off >>= 1)
            acc += __shfl_xor_sync(0xFFFFFFFFu, acc, off);
        if (lane == 0) {
            g_part[blockIdx.x] = acc;
            __threadfence();
            // Wraps back to 0 once all GRID blocks have arrived.
            s_ticket = atomicInc(&g_count, GRID - 1);
        }
    }
    __syncthreads();

    // Last block to arrive performs the final reduction (partials are L2-hot).
    if (s_ticket == GRID - 1) {
        double a = 0.0;
        #pragma unroll
        for (int j = 0; j < GRID / TPB; j++)
            a += (double)g_part[tid + j * TPB];

        #pragma unroll
        for (int off = 16; off > 0; off >>= 1)
            a += __shfl_xor_sync(0xFFFFFFFFu, a, off);

        __shared__ double ds[TPB / 32];
        if (lane == 0) ds[warp] = a;
        __syncthreads();

        if (warp == 0) {
            a = (lane < TPB / 32) ? ds[lane] : 0.0;
            #pragma unroll
            for (int off = 4; off > 0; off >>= 1)
                a += __shfl_xor_sync(0xFFFFFFFFu, a, off);
            if (lane == 0) out[0] = (float)(a / (double)nrows);
        }
    }
}

extern "C" void kernel_launch(void* const* d_in, const int* in_sizes, int n_in,
                              void* d_out, int out_size) {
    const float4* in = (const float4*)d_in[0];
    float* out = (float*)d_out;
    int nrows = in_sizes[0] / 24;  // 24 floats per row

    loss_kernel<<<GRID, TPB>>>(in, nrows, out);
}

// round 4
// speedup vs baseline: 1.0034x; 1.0034x over previous
#include <cuda_runtime.h>

#define TPB      256
#define MAXGRID  16384   // 4194304 rows / 256

// Per-block partials: fully overwritten each launch (graph-deterministic).
__device__ float g_part[MAXGRID];
// atomicInc with wrap (grid-1) returns to 0 after each complete launch.
__device__ unsigned int g_count;

__device__ __forceinline__ float group_loss(float4 p, float4 q, float4 r) {
    float ax = p.y, ay = p.z, az = p.w;
    float bx = q.y, by = q.z, bz = q.w;
    float cx = r.y, cy = r.z, cz = r.w;

    float ia = rsqrtf(ax * ax + ay * ay + az * az);
    float ib = rsqrtf(bx * bx + by * by + bz * bz);
    float ic = rsqrtf(cx * cx + cy * cy + cz * cz);
    ax *= ia; ay *= ia; az *= ia;
    bx *= ib; by *= ib; bz *= ib;
    cx *= ic; cy *= ic; cz *= ic;

    float daa = ax * ax + ay * ay + az * az - 1.0f;
    float dbb = bx * bx + by * by + bz * bz - 1.0f;
    float dcc = cx * cx + cy * cy + cz * cz - 1.0f;
    float dab = ax * bx + ay * by + az * bz;
    float dac = ax * cx + ay * cy + az * cz;
    float dbc = bx * cx + by * cy + bz * cz;

    return daa * daa + dbb * dbb + dcc * dcc
         + 2.0f * (dab * dab + dac * dac + dbc * dbc);
}

__global__ void __launch_bounds__(TPB) loss_kernel(const float4* __restrict__ in,
                                                   int nrows, int grid,
                                                   float* __restrict__ out) {
    const int tid = threadIdx.x;
    const int row = blockIdx.x * TPB + tid;

    float acc = 0.0f;
    if (row < nrows) {
        const float4* __restrict__ r = in + (size_t)row * 6;
        // 6 front-batched streaming LDG.128 (data touched exactly once).
        float4 r0 = __ldcs(r + 0);
        float4 r1 = __ldcs(r + 1);
        float4 r2 = __ldcs(r + 2);
        float4 r3 = __ldcs(r + 3);
        float4 r4 = __ldcs(r + 4);
        float4 r5 = __ldcs(r + 5);
        acc  = group_loss(r0, r1, r2);
        acc += group_loss(r3, r4, r5);
    }

    // Block reduction.
    #pragma unroll
    for (int off = 16; off > 0; off >>= 1)
        acc += __shfl_xor_sync(0xFFFFFFFFu, acc, off);

    __shared__ float ws[TPB / 32];
    __shared__ unsigned int s_ticket;
    const int lane = tid & 31;
    const int warp = tid >> 5;
    if (lane == 0) ws[warp] = acc;
    __syncthreads();

    if (warp == 0) {
        acc = (lane < TPB / 32) ? ws[lane] : 0.0f;
        #pragma unroll
        for (int off = 4; off > 0; off >>= 1)
            acc += __shfl_xor_sync(0xFFFFFFFFu, acc, off);
        if (lane == 0) {
            g_part[blockIdx.x] = acc;
            __threadfence();
            s_ticket = atomicInc(&g_count, (unsigned)grid - 1);
        }
    }
    __syncthreads();

    // Last block to arrive reduces all partials (L2-hot).
    if (s_ticket == (unsigned)grid - 1) {
        double a = 0.0;
        for (int i = tid; i < grid; i += TPB)
            a += (double)g_part[i];

        #pragma unroll
        for (int off = 16; off > 0; off >>= 1)
            a += __shfl_xor_sync(0xFFFFFFFFu, a, off);

        __shared__ double ds[TPB / 32];
        if (lane == 0) ds[warp] = a;
        __syncthreads();

        if (warp == 0) {
            a = (lane < TPB / 32) ? ds[lane] : 0.0;
            #pragma unroll
            for (int off = 4; off > 0; off >>= 1)
                a += __shfl_xor_sync(0xFFFFFFFFu, a, off);
            if (lane == 0) out[0] = (float)(a / (double)nrows);
        }
    }
}

extern "C" void kernel_launch(void* const* d_in, const int* in_sizes, int n_in,
                              void* d_out, int out_size) {
    const float4* in = (const float4*)d_in[0];
    float* out = (float*)d_out;
    int nrows = in_sizes[0] / 24;  // 24 floats per row
    int grid = (nrows + TPB - 1) / TPB;
    if (grid > MAXGRID) grid = MAXGRID;  // safety: shapes are fixed at 16384

    loss_kernel<<<grid, TPB>>>(in, nrows, grid, out);
}